// round 1
// baseline (speedup 1.0000x reference)
#include <cuda_runtime.h>
#include <cstdint>

// Problem constants (fixed by the dataset)
#define BQ   2      // batch
#define NCAM 6      // cameras
#define CCH  256    // channels
#define MQ   900    // queries
#define NLVL 4      // pyramid levels
#define EPSV 1e-5f

// Level shapes
__constant__ int c_H[NLVL]  = {116, 58, 29, 15};
__constant__ int c_W[NLVL]  = {200, 100, 50, 25};
__constant__ int c_HW[NLVL] = {23200, 5800, 1450, 375};

#define NENT (NCAM * NLVL)   // 24 candidate (camera, level) entries per query

__global__ __launch_bounds__(CCH, 4)
void FeatureSampler_kernel(const float* __restrict__ f0,
                           const float* __restrict__ f1,
                           const float* __restrict__ f2,
                           const float* __restrict__ f3,
                           const float* __restrict__ refpts,
                           const float* __restrict__ l2i,
                           float* __restrict__ out)
{
    const int bm = blockIdx.x;          // b * MQ + m
    const int b  = bm / MQ;
    const int c  = threadIdx.x;         // channel index

    __shared__ const float* s_base[NENT];
    __shared__ int   s_HW[NENT];
    __shared__ int   s_idx[NENT][4];
    __shared__ float s_w[NENT][4];
    __shared__ int   s_act[NENT];
    __shared__ float s_valid[NCAM];
    __shared__ int   s_list[NENT];
    __shared__ int   s_ne;

    // ---- Phase 1: threads 0..23 build per-(camera,level) sampling entries ----
    if (threadIdx.x < NENT) {
        const int t   = threadIdx.x;
        const int n   = t >> 2;          // camera
        const int lvl = t & 3;           // level

        // Denormalize reference point into point-cloud range
        const float* rp = refpts + (size_t)bm * 3;
        float rx = rp[0] * 122.4f - 61.2f;
        float ry = rp[1] * 122.4f - 61.2f;
        float rz = rp[2] * 20.0f  - 10.0f;

        const float* Mt = l2i + (size_t)(b * NCAM + n) * 16;
        float cx = Mt[0]*rx + Mt[1]*ry + Mt[2] *rz + Mt[3];
        float cy = Mt[4]*rx + Mt[5]*ry + Mt[6] *rz + Mt[7];
        float cz = Mt[8]*rx + Mt[9]*ry + Mt[10]*rz + Mt[11];

        bool vcam = (cz > EPSV);
        if (lvl == 0) s_valid[n] = vcam ? 1.0f : 0.0f;

        float inv = 1.0f / (cz + EPSV);
        // grid_sample denorm cancels: sample coord = px - 0.5 at every level
        float x = cx * inv - 0.5f;
        float y = cy * inv - 0.5f;

        const int W  = c_W[lvl];
        const int H  = c_H[lvl];
        const int HW = c_HW[lvl];

        int active = 0;
        // Only proceed if some corner can be in bounds (also rejects NaN/Inf)
        if (vcam && (x > -1.0f) && (x < (float)W) && (y > -1.0f) && (y < (float)H)) {
            float x0f = floorf(x), y0f = floorf(y);
            float wx1 = x - x0f, wx0 = 1.0f - wx1;
            float wy1 = y - y0f, wy0 = 1.0f - wy1;

            bool vx0 = (x0f >= 0.0f)        && (x0f <= (float)(W - 1));
            bool vx1 = (x0f + 1.0f >= 0.0f) && (x0f + 1.0f <= (float)(W - 1));
            bool vy0 = (y0f >= 0.0f)        && (y0f <= (float)(H - 1));
            bool vy1 = (y0f + 1.0f >= 0.0f) && (y0f + 1.0f <= (float)(H - 1));

            int xi0 = (int)fminf(fmaxf(x0f,        0.0f), (float)(W - 1));
            int xi1 = (int)fminf(fmaxf(x0f + 1.0f, 0.0f), (float)(W - 1));
            int yi0 = (int)fminf(fmaxf(y0f,        0.0f), (float)(H - 1));
            int yi1 = (int)fminf(fmaxf(y0f + 1.0f, 0.0f), (float)(H - 1));

            float w00 = (vx0 && vy0) ? (wx0 * wy0) : 0.0f;
            float w01 = (vx1 && vy0) ? (wx1 * wy0) : 0.0f;
            float w10 = (vx0 && vy1) ? (wx0 * wy1) : 0.0f;
            float w11 = (vx1 && vy1) ? (wx1 * wy1) : 0.0f;

            if ((w00 != 0.0f) || (w01 != 0.0f) || (w10 != 0.0f) || (w11 != 0.0f)) {
                active = 1;
                const float* fl = (lvl == 0) ? f0 : (lvl == 1) ? f1 : (lvl == 2) ? f2 : f3;
                s_base[t]   = fl + (size_t)(b * NCAM + n) * CCH * HW;
                s_HW[t]     = HW;
                s_idx[t][0] = yi0 * W + xi0;
                s_idx[t][1] = yi0 * W + xi1;
                s_idx[t][2] = yi1 * W + xi0;
                s_idx[t][3] = yi1 * W + xi1;
                s_w[t][0] = w00;  s_w[t][1] = w01;
                s_w[t][2] = w10;  s_w[t][3] = w11;
            }
        }
        s_act[t] = active;
    }
    __syncthreads();

    // ---- Deterministic compaction (thread 0; order fixed => FP-deterministic) ----
    if (threadIdx.x == 0) {
        int ne = 0;
        #pragma unroll
        for (int e = 0; e < NENT; e++)
            if (s_act[e]) s_list[ne++] = e;
        s_ne = ne;
    }
    __syncthreads();

    const float cnt = s_valid[0] + s_valid[1] + s_valid[2] +
                      s_valid[3] + s_valid[4] + s_valid[5];
    const int ne = s_ne;

    // ---- Phase 2: all 256 threads gather their channel over the active entries ----
    float acc0 = 0.0f, acc1 = 0.0f;
    int k = 0;
    // unroll by 2 with independent accumulators to expose MLP
    for (; k + 1 < ne; k += 2) {
        int ea = s_list[k];
        int eb = s_list[k + 1];
        const float* pa = s_base[ea] + (size_t)c * s_HW[ea];
        const float* pb = s_base[eb] + (size_t)c * s_HW[eb];
        float a0 = __ldg(pa + s_idx[ea][0]);
        float a1 = __ldg(pa + s_idx[ea][1]);
        float a2 = __ldg(pa + s_idx[ea][2]);
        float a3 = __ldg(pa + s_idx[ea][3]);
        float b0 = __ldg(pb + s_idx[eb][0]);
        float b1 = __ldg(pb + s_idx[eb][1]);
        float b2 = __ldg(pb + s_idx[eb][2]);
        float b3 = __ldg(pb + s_idx[eb][3]);
        acc0 += s_w[ea][0]*a0 + s_w[ea][1]*a1 + s_w[ea][2]*a2 + s_w[ea][3]*a3;
        acc1 += s_w[eb][0]*b0 + s_w[eb][1]*b1 + s_w[eb][2]*b2 + s_w[eb][3]*b3;
    }
    if (k < ne) {
        int ea = s_list[k];
        const float* pa = s_base[ea] + (size_t)c * s_HW[ea];
        acc0 += s_w[ea][0]*__ldg(pa + s_idx[ea][0])
              + s_w[ea][1]*__ldg(pa + s_idx[ea][1])
              + s_w[ea][2]*__ldg(pa + s_idx[ea][2])
              + s_w[ea][3]*__ldg(pa + s_idx[ea][3]);
    }

    float result = (acc0 + acc1) * 0.25f / (cnt + EPSV);
    out[(size_t)bm * CCH + c] = result;
}

extern "C" void kernel_launch(void* const* d_in, const int* in_sizes, int n_in,
                              void* d_out, int out_size)
{
    const float* f0  = (const float*)d_in[0];
    const float* f1  = (const float*)d_in[1];
    const float* f2  = (const float*)d_in[2];
    const float* f3  = (const float*)d_in[3];
    const float* rp  = (const float*)d_in[4];
    const float* l2i = (const float*)d_in[5];
    float* out = (float*)d_out;

    dim3 grid(BQ * MQ);
    dim3 block(CCH);
    FeatureSampler_kernel<<<grid, block>>>(f0, f1, f2, f3, rp, l2i, out);
}

// round 2
// speedup vs baseline: 1.0060x; 1.0060x over previous
#include <cuda_runtime.h>
#include <cstdint>

// Problem constants (fixed by the dataset)
#define BQ   2      // batch
#define NCAM 6      // cameras
#define CCH  256    // channels
#define MQ   900    // queries
#define NLVL 4      // pyramid levels
#define EPSV 1e-5f

// Level shapes
__constant__ int c_H[NLVL]  = {116, 58, 29, 15};
__constant__ int c_W[NLVL]  = {200, 100, 50, 25};
__constant__ int c_HW[NLVL] = {23200, 5800, 1450, 375};

#define NENT (NCAM * NLVL)   // 24 candidate (camera, level) entries per query

__device__ __forceinline__ float sel4(float4 q, int s) {
    return (s == 0) ? q.x : (s == 1) ? q.y : (s == 2) ? q.z : q.w;
}

__global__ __launch_bounds__(CCH, 5)
void FeatureSampler_kernel(const float* __restrict__ f0,
                           const float* __restrict__ f1,
                           const float* __restrict__ f2,
                           const float* __restrict__ f3,
                           const float* __restrict__ refpts,
                           const float* __restrict__ l2i,
                           float* __restrict__ out)
{
    const int bm = blockIdx.x;          // b * MQ + m
    const int b  = bm / MQ;
    const int c  = threadIdx.x;         // channel index

    __shared__ const float* s_base[NENT];   // level base + (b*N+n)*C*HW
    __shared__ int   s_HW[NENT];
    __shared__ int   s_idx[NENT][4];        // 4 corner offsets within channel plane
    __shared__ float s_w[NENT][4];
    __shared__ int   s_act[NENT];           // 0 inactive, 1 fast (float4), 2 slow
    __shared__ float s_valid[NCAM];
    __shared__ int   s_list[NENT];
    __shared__ int   s_ne;

    // ---- Phase 1: threads 0..23 build per-(camera,level) sampling entries ----
    if (threadIdx.x < NENT) {
        const int t   = threadIdx.x;
        const int n   = t >> 2;          // camera
        const int lvl = t & 3;           // level

        // Denormalize reference point into point-cloud range
        const float* rp = refpts + (size_t)bm * 3;
        float rx = rp[0] * 122.4f - 61.2f;
        float ry = rp[1] * 122.4f - 61.2f;
        float rz = rp[2] * 20.0f  - 10.0f;

        const float* Mt = l2i + (size_t)(b * NCAM + n) * 16;
        float cx = Mt[0]*rx + Mt[1]*ry + Mt[2] *rz + Mt[3];
        float cy = Mt[4]*rx + Mt[5]*ry + Mt[6] *rz + Mt[7];
        float cz = Mt[8]*rx + Mt[9]*ry + Mt[10]*rz + Mt[11];

        bool vcam = (cz > EPSV);
        if (lvl == 0) s_valid[n] = vcam ? 1.0f : 0.0f;

        float inv = 1.0f / (cz + EPSV);
        // grid_sample denorm cancels: sample coord = px - 0.5 at every level
        float x = cx * inv - 0.5f;
        float y = cy * inv - 0.5f;

        const int W  = c_W[lvl];
        const int H  = c_H[lvl];
        const int HW = c_HW[lvl];

        int active = 0;
        if (vcam && (x > -1.0f) && (x < (float)W) && (y > -1.0f) && (y < (float)H)) {
            float x0f = floorf(x), y0f = floorf(y);
            float wx1 = x - x0f, wx0 = 1.0f - wx1;
            float wy1 = y - y0f, wy0 = 1.0f - wy1;

            bool vx0 = (x0f >= 0.0f)        && (x0f <= (float)(W - 1));
            bool vx1 = (x0f + 1.0f >= 0.0f) && (x0f + 1.0f <= (float)(W - 1));
            bool vy0 = (y0f >= 0.0f)        && (y0f <= (float)(H - 1));
            bool vy1 = (y0f + 1.0f >= 0.0f) && (y0f + 1.0f <= (float)(H - 1));

            int xi0 = (int)fminf(fmaxf(x0f,        0.0f), (float)(W - 1));
            int xi1 = (int)fminf(fmaxf(x0f + 1.0f, 0.0f), (float)(W - 1));
            int yi0 = (int)fminf(fmaxf(y0f,        0.0f), (float)(H - 1));
            int yi1 = (int)fminf(fmaxf(y0f + 1.0f, 0.0f), (float)(H - 1));

            float w00 = (vx0 && vy0) ? (wx0 * wy0) : 0.0f;
            float w01 = (vx1 && vy0) ? (wx1 * wy0) : 0.0f;
            float w10 = (vx0 && vy1) ? (wx0 * wy1) : 0.0f;
            float w11 = (vx1 && vy1) ? (wx1 * wy1) : 0.0f;

            if ((w00 != 0.0f) || (w01 != 0.0f) || (w10 != 0.0f) || (w11 != 0.0f)) {
                // fast path: both x-corners adjacent, and xi0 <= W-4 so every
                // byte the float4/scalar loads touch stays inside the channel row
                bool fast = (xi1 == xi0 + 1) && (xi0 + 4 <= W);
                active = fast ? 1 : 2;
                const float* fl = (lvl == 0) ? f0 : (lvl == 1) ? f1 : (lvl == 2) ? f2 : f3;
                s_base[t]   = fl + (size_t)(b * NCAM + n) * CCH * HW;
                s_HW[t]     = HW;
                s_idx[t][0] = yi0 * W + xi0;
                s_idx[t][1] = yi0 * W + xi1;
                s_idx[t][2] = yi1 * W + xi0;
                s_idx[t][3] = yi1 * W + xi1;
                s_w[t][0] = w00;  s_w[t][1] = w01;
                s_w[t][2] = w10;  s_w[t][3] = w11;
            }
        }
        s_act[t] = active;
    }
    __syncthreads();

    // ---- Deterministic compaction (thread 0; fixed order => FP-deterministic) ----
    if (threadIdx.x == 0) {
        int ne = 0;
        #pragma unroll
        for (int e = 0; e < NENT; e++)
            if (s_act[e]) s_list[ne++] = e;
        s_ne = ne;
    }
    __syncthreads();

    const float cnt = s_valid[0] + s_valid[1] + s_valid[2] +
                      s_valid[3] + s_valid[4] + s_valid[5];
    const int ne = s_ne;

    // ---- Phase 2: all 256 threads gather their channel over the active entries ----
    float acc = 0.0f;
    for (int k = 0; k < ne; k++) {
        const int e = s_list[k];
        const float* p = s_base[e] + (size_t)c * s_HW[e];
        const float w0 = s_w[e][0], w1 = s_w[e][1];
        const float w2 = s_w[e][2], w3 = s_w[e][3];
        const int i0 = s_idx[e][0];
        const int i2 = s_idx[e][2];

        if (s_act[e] == 1) {
            // fast: one aligned float4 per row covers both x-corners for sel<3;
            // predicated scalar load only for lanes whose pair straddles 16B
            uintptr_t a0 = (uintptr_t)(p + i0);
            uintptr_t a1 = (uintptr_t)(p + i2);
            int sel0 = (int)((a0 >> 2) & 3);
            int sel1 = (int)((a1 >> 2) & 3);
            float4 q0 = __ldg((const float4*)(a0 & ~(uintptr_t)15));
            float4 q1 = __ldg((const float4*)(a1 & ~(uintptr_t)15));
            float v00 = sel4(q0, sel0);
            float v10 = sel4(q1, sel1);
            float v01 = (sel0 < 3) ? sel4(q0, sel0 + 1) : __ldg(p + i0 + 1);
            float v11 = (sel1 < 3) ? sel4(q1, sel1 + 1) : __ldg(p + i2 + 1);
            acc += w0*v00 + w1*v01 + w2*v10 + w3*v11;
        } else {
            // slow: edge / clamped entries, 4 scalar gathers (weights already zeroed)
            float v00 = __ldg(p + i0);
            float v01 = __ldg(p + s_idx[e][1]);
            float v10 = __ldg(p + i2);
            float v11 = __ldg(p + s_idx[e][3]);
            acc += w0*v00 + w1*v01 + w2*v10 + w3*v11;
        }
    }

    float result = acc * 0.25f / (cnt + EPSV);
    out[(size_t)bm * CCH + c] = result;
}

extern "C" void kernel_launch(void* const* d_in, const int* in_sizes, int n_in,
                              void* d_out, int out_size)
{
    const float* f0  = (const float*)d_in[0];
    const float* f1  = (const float*)d_in[1];
    const float* f2  = (const float*)d_in[2];
    const float* f3  = (const float*)d_in[3];
    const float* rp  = (const float*)d_in[4];
    const float* l2i = (const float*)d_in[5];
    float* out = (float*)d_out;

    dim3 grid(BQ * MQ);
    dim3 block(CCH);
    FeatureSampler_kernel<<<grid, block>>>(f0, f1, f2, f3, rp, l2i, out);
}